// round 1
// baseline (speedup 1.0000x reference)
#include <cuda_runtime.h>
#include <cuda_bf16.h>
#include <math.h>

#define B_SZ    2
#define SEQ_L   2048
#define D_MODEL 1024
#define D_INNER 2048
#define D_STATE 16
#define D_CONV  4
#define DT_RANK 64
#define NTOK    (B_SZ * SEQ_L)          // 4096

// ---------------------------------------------------------------- scratch ---
__device__ __align__(128) float g_hnorm[(size_t)NTOK * D_MODEL];     // 16.8 MB
__device__ __align__(128) float g_xz[(size_t)NTOK * 2 * D_INNER];    // 67 MB
__device__ __align__(128) float g_xconv[(size_t)NTOK * D_INNER];     // 33.5 MB
__device__ __align__(128) float g_xdbl[(size_t)NTOK * 96];           // 1.6 MB
__device__ __align__(128) float g_dt[(size_t)NTOK * D_INNER];        // 33.5 MB
__device__ __align__(128) float g_y[(size_t)NTOK * D_INNER];         // 33.5 MB

// ------------------------------------------------------------- layernorm ----
__global__ void ln_kernel(const float* __restrict__ x,
                          const float* __restrict__ g,
                          const float* __restrict__ be,
                          float* __restrict__ o)
{
    __shared__ float sred[64];
    const int row = blockIdx.x;
    const float4* xr = reinterpret_cast<const float4*>(x + (size_t)row * D_MODEL);
    float4 v = xr[threadIdx.x];
    float s = v.x + v.y + v.z + v.w;
    float q = v.x*v.x + v.y*v.y + v.z*v.z + v.w*v.w;
    #pragma unroll
    for (int off = 16; off; off >>= 1) {
        s += __shfl_xor_sync(0xffffffffu, s, off);
        q += __shfl_xor_sync(0xffffffffu, q, off);
    }
    const int warp = threadIdx.x >> 5, lane = threadIdx.x & 31;
    if (lane == 0) { sred[warp] = s; sred[32 + warp] = q; }
    __syncthreads();
    if (threadIdx.x == 0) {
        float ts = 0.f, tq = 0.f;
        #pragma unroll
        for (int i = 0; i < 8; i++) { ts += sred[i]; tq += sred[32 + i]; }
        float mean = ts * (1.f / D_MODEL);
        float var  = tq * (1.f / D_MODEL) - mean * mean;
        sred[0] = mean;
        sred[1] = rsqrtf(var + 1e-5f);
    }
    __syncthreads();
    const float mean = sred[0], inv = sred[1];
    float4 gg = reinterpret_cast<const float4*>(g)[threadIdx.x];
    float4 bb = reinterpret_cast<const float4*>(be)[threadIdx.x];
    float4 out;
    out.x = (v.x - mean) * inv * gg.x + bb.x;
    out.y = (v.y - mean) * inv * gg.y + bb.y;
    out.z = (v.z - mean) * inv * gg.z + bb.z;
    out.w = (v.w - mean) * inv * gg.w + bb.w;
    reinterpret_cast<float4*>(o + (size_t)row * D_MODEL)[threadIdx.x] = out;
}

// ------------------------------------------------------------- SIMT sgemm ---
// C[M,N] = A[M,K(lda)] * B[N,K(ldb)]^T   (both K-contiguous, "NT")
// epi 0: store    epi 1: softplus(c + aux[n])    epi 2: c + aux[m*ldc+n]
template<int BM, int BN, int BK, int TM, int TN, int NTH>
__global__ void __launch_bounds__(NTH) sgemm_nt(
    int M, int N, int K,
    const float* __restrict__ A, int lda,
    const float* __restrict__ Bm, int ldb,
    float* __restrict__ C, int ldc,
    int epi, const float* __restrict__ aux)
{
    __shared__ float As[BK][BM];
    __shared__ float Bs[BK][BN];
    const int tid = threadIdx.x;
    const int m0 = blockIdx.y * BM;
    const int n0 = blockIdx.x * BN;
    constexpr int TX = BN / TN;
    const int tx = tid % TX, ty = tid / TX;

    float acc[TM][TN];
    #pragma unroll
    for (int i = 0; i < TM; i++)
        #pragma unroll
        for (int j = 0; j < TN; j++) acc[i][j] = 0.f;

    constexpr int AVEC = (BM * BK / NTH >= 4) ? 4 : 2;
    constexpr int A_TPR = BK / AVEC;
    constexpr int A_RPP = NTH / A_TPR;
    constexpr int BVEC = (BN * BK / NTH >= 4) ? 4 : 2;
    constexpr int B_TPR = BK / BVEC;
    constexpr int B_RPP = NTH / B_TPR;

    for (int k0 = 0; k0 < K; k0 += BK) {
        __syncthreads();
        // -------- load A tile (transposed into smem), no guards needed (M%BM==0, K%BK==0)
        #pragma unroll
        for (int r0 = 0; r0 < BM; r0 += A_RPP) {
            int row = r0 + tid / A_TPR;
            int kc  = (tid % A_TPR) * AVEC;
            const float* src = A + (size_t)(m0 + row) * lda + k0 + kc;
            if (AVEC == 4) {
                float4 v = *reinterpret_cast<const float4*>(src);
                As[kc    ][row] = v.x; As[kc + 1][row] = v.y;
                As[kc + 2][row] = v.z; As[kc + 3][row] = v.w;
            } else {
                float2 v = *reinterpret_cast<const float2*>(src);
                As[kc][row] = v.x; As[kc + 1][row] = v.y;
            }
        }
        // -------- load B tile (guard ragged N)
        #pragma unroll
        for (int r0 = 0; r0 < BN; r0 += B_RPP) {
            int row = r0 + tid / B_TPR;
            int kc  = (tid % B_TPR) * BVEC;
            int n   = n0 + row;
            if (BVEC == 4) {
                float4 v = (n < N)
                    ? *reinterpret_cast<const float4*>(Bm + (size_t)n * ldb + k0 + kc)
                    : make_float4(0.f, 0.f, 0.f, 0.f);
                Bs[kc    ][row] = v.x; Bs[kc + 1][row] = v.y;
                Bs[kc + 2][row] = v.z; Bs[kc + 3][row] = v.w;
            } else {
                float2 v = (n < N)
                    ? *reinterpret_cast<const float2*>(Bm + (size_t)n * ldb + k0 + kc)
                    : make_float2(0.f, 0.f);
                Bs[kc][row] = v.x; Bs[kc + 1][row] = v.y;
            }
        }
        __syncthreads();
        // -------- compute
        #pragma unroll
        for (int k = 0; k < BK; k++) {
            float a[TM], b[TN];
            #pragma unroll
            for (int v = 0; v < TM / 4; v++) {
                float4 t = *reinterpret_cast<const float4*>(&As[k][ty * 4 + v * (BM / 2)]);
                a[v*4+0] = t.x; a[v*4+1] = t.y; a[v*4+2] = t.z; a[v*4+3] = t.w;
            }
            #pragma unroll
            for (int v = 0; v < TN / 4; v++) {
                float4 t = *reinterpret_cast<const float4*>(&Bs[k][tx * 4 + v * (BN / 2)]);
                b[v*4+0] = t.x; b[v*4+1] = t.y; b[v*4+2] = t.z; b[v*4+3] = t.w;
            }
            #pragma unroll
            for (int i = 0; i < TM; i++)
                #pragma unroll
                for (int j = 0; j < TN; j++)
                    acc[i][j] = fmaf(a[i], b[j], acc[i][j]);
        }
    }
    // -------- epilogue
    #pragma unroll
    for (int i = 0; i < TM; i++) {
        int m = m0 + ty * 4 + (i & 3) + (i >> 2) * (BM / 2);
        #pragma unroll
        for (int j = 0; j < TN; j++) {
            int n = n0 + tx * 4 + (j & 3) + (j >> 2) * (BN / 2);
            if (n < N) {
                float v = acc[i][j];
                if (epi == 1) {
                    v += aux[n];
                    v = (v > 20.f) ? v : log1pf(expf(v));   // softplus
                } else if (epi == 2) {
                    v += aux[(size_t)m * ldc + n];          // residual
                }
                C[(size_t)m * ldc + n] = v;
            }
        }
    }
}

// -------------------------------------------------- depthwise conv + SiLU ---
__global__ void conv_silu_kernel(const float* __restrict__ xz,
                                 const float* __restrict__ w,
                                 const float* __restrict__ bias,
                                 float* __restrict__ out)
{
    const int idx = blockIdx.x * blockDim.x + threadIdx.x;     // B*L*D_INNER
    if (idx >= B_SZ * SEQ_L * D_INNER) return;
    const int c = idx & (D_INNER - 1);
    const int t = (idx >> 11) & (SEQ_L - 1);
    const int b = idx >> 22;
    const float* col = xz + (size_t)(b * SEQ_L) * (2 * D_INNER) + c;
    const float4 wv = reinterpret_cast<const float4*>(w)[c];
    float acc = bias[c];
    if (t >= 3) {
        acc += col[(size_t)(t - 3) * 4096] * wv.x
             + col[(size_t)(t - 2) * 4096] * wv.y
             + col[(size_t)(t - 1) * 4096] * wv.z
             + col[(size_t)(t    ) * 4096] * wv.w;
    } else {
        const float wj[4] = {wv.x, wv.y, wv.z, wv.w};
        #pragma unroll
        for (int j = 0; j < 4; j++) {
            int tt = t - 3 + j;
            if (tt >= 0) acc += col[(size_t)tt * 4096] * wj[j];
        }
    }
    const float sig = 1.f / (1.f + expf(-acc));
    out[idx] = acc * sig;
}

// ---------------------------------------------- selective scan (fused) ------
// 16 lanes per channel, one state each. h_t = exp(dt*A_s)*h + dt*B_s*x,
// y = sum_s h*C_s ; fused: out = (y + x*D)*silu(z)
__global__ void __launch_bounds__(256) scan_fuse_kernel(
    const float* __restrict__ dt,
    const float* __restrict__ xconv,
    const float* __restrict__ xdbl,
    const float* __restrict__ xz,
    const float* __restrict__ A_log,
    const float* __restrict__ Dp,
    float* __restrict__ y)
{
    const int b     = blockIdx.x >> 7;               // 256 blocks: 128 per batch
    const int dbase = (blockIdx.x & 127) << 4;       // 16 channels / block
    const int lane  = threadIdx.x & 31;
    const int warp  = threadIdx.x >> 5;
    const int s     = lane & 15;
    const int half  = lane >> 4;
    const int d     = dbase + warp * 2 + half;

    const float Acoef = -expf(A_log[d * D_STATE + s]);
    const float Dv    = Dp[d];
    float h = 0.f;

    const float* dt_p = dt    + (size_t)b * SEQ_L * D_INNER + d;
    const float* x_p  = xconv + (size_t)b * SEQ_L * D_INNER + d;
    const float* B_p  = xdbl  + (size_t)b * SEQ_L * 96 + DT_RANK + s;
    const float* C_p  = B_p + D_STATE;
    const float* z_p  = xz    + (size_t)b * SEQ_L * (2 * D_INNER) + D_INNER + d;
    float*       y_p  = y     + (size_t)b * SEQ_L * D_INNER + d;

    #pragma unroll 4
    for (int t = 0; t < SEQ_L; ++t) {
        const float dtv = dt_p[(size_t)t * D_INNER];
        const float xv  = x_p [(size_t)t * D_INNER];
        const float Bv  = B_p [(size_t)t * 96];
        const float Cv  = C_p [(size_t)t * 96];

        const float p = __expf(Acoef * dtv);
        h = fmaf(p, h, dtv * Bv * xv);
        float yp = h * Cv;
        yp += __shfl_xor_sync(0xffffffffu, yp, 8);
        yp += __shfl_xor_sync(0xffffffffu, yp, 4);
        yp += __shfl_xor_sync(0xffffffffu, yp, 2);
        yp += __shfl_xor_sync(0xffffffffu, yp, 1);
        if (s == 0) {
            const float zv  = z_p[(size_t)t * (2 * D_INNER)];
            const float sig = 1.f / (1.f + __expf(-zv));
            y_p[(size_t)t * D_INNER] = (yp + xv * Dv) * (zv * sig);
        }
    }
}

// ----------------------------------------------------------------- launch ---
extern "C" void kernel_launch(void* const* d_in, const int* in_sizes, int n_in,
                              void* d_out, int out_size)
{
    const float* hs    = (const float*)d_in[0];   // hidden_states [B,L,1024]
    const float* ln_g  = (const float*)d_in[1];
    const float* ln_b  = (const float*)d_in[2];
    const float* inw   = (const float*)d_in[3];   // [4096,1024]
    const float* convw = (const float*)d_in[4];   // [2048,4]
    const float* convb = (const float*)d_in[5];
    const float* xpw   = (const float*)d_in[6];   // [96,2048]
    const float* dtw   = (const float*)d_in[7];   // [2048,64]
    const float* dtb   = (const float*)d_in[8];
    const float* alog  = (const float*)d_in[9];   // [2048,16]
    const float* Dv    = (const float*)d_in[10];
    const float* outw  = (const float*)d_in[11];  // [1024,2048]

    float *hnorm, *xz, *xconv, *xdbl, *dtbuf, *ybuf;
    cudaGetSymbolAddress((void**)&hnorm, g_hnorm);
    cudaGetSymbolAddress((void**)&xz,    g_xz);
    cudaGetSymbolAddress((void**)&xconv, g_xconv);
    cudaGetSymbolAddress((void**)&xdbl,  g_xdbl);
    cudaGetSymbolAddress((void**)&dtbuf, g_dt);
    cudaGetSymbolAddress((void**)&ybuf,  g_y);

    // 1. LayerNorm
    ln_kernel<<<NTOK, 256>>>(hs, ln_g, ln_b, hnorm);

    // 2. in_proj: xz[4096,4096] = hnorm[4096,1024] @ inw^T
    sgemm_nt<128,128,8,8,8,256><<<dim3(32, 32), 256>>>(
        NTOK, 4096, 1024, hnorm, 1024, inw, 1024, xz, 4096, 0, nullptr);

    // 3. depthwise causal conv + SiLU on x half of xz
    conv_silu_kernel<<<(B_SZ * SEQ_L * D_INNER) / 256, 256>>>(xz, convw, convb, xconv);

    // 4. x_proj: xdbl[4096,96] = xconv @ xpw^T   (ragged N)
    sgemm_nt<32,128,8,4,8,128><<<dim3(1, 128), 128>>>(
        NTOK, 96, 2048, xconv, 2048, xpw, 2048, xdbl, 96, 0, nullptr);

    // 5. dt_proj + softplus: dt[4096,2048] = softplus(xdbl[:, :64] @ dtw^T + dtb)
    sgemm_nt<128,128,8,8,8,256><<<dim3(16, 32), 256>>>(
        NTOK, 2048, 64, xdbl, 96, dtw, 64, dtbuf, 2048, 1, dtb);

    // 6. selective scan fused with (+x*D)*silu(z)
    scan_fuse_kernel<<<256, 256>>>(dtbuf, xconv, xdbl, xz, alog, Dv, ybuf);

    // 7. out_proj + residual -> d_out
    sgemm_nt<128,128,8,8,8,256><<<dim3(8, 32), 256>>>(
        NTOK, 1024, 2048, ybuf, 2048, outw, 2048, (float*)d_out, 1024, 2, hs);
}

// round 3
// speedup vs baseline: 1.3974x; 1.3974x over previous
#include <cuda_runtime.h>
#include <cuda_fp16.h>
#include <math.h>
#include <stdint.h>

#define B_SZ    2
#define SEQ_L   2048
#define D_MODEL 1024
#define D_INNER 2048
#define D_STATE 16
#define DT_RANK 64
#define NTOK    (B_SZ * SEQ_L)          // 4096

// ---------------------------------------------------------------- scratch ---
__device__ __align__(128) __half g_hnorm_h[(size_t)NTOK * D_MODEL];
__device__ __align__(128) float  g_xz[(size_t)NTOK * 2 * D_INNER];
__device__ __align__(128) float  g_xconv[(size_t)NTOK * D_INNER];
__device__ __align__(128) float  g_xdbl[(size_t)NTOK * 96];
__device__ __align__(128) float  g_xpart[8][(size_t)NTOK * 96];
__device__ __align__(128) float  g_dt[(size_t)NTOK * D_INNER];
__device__ __align__(128) __half g_y_h[(size_t)NTOK * D_INNER];
__device__ __align__(128) __half g_w_in_h[(size_t)2 * D_INNER * D_MODEL];
__device__ __align__(128) __half g_w_out_h[(size_t)D_MODEL * D_INNER];

// ------------------------------------------------------------- helpers ------
__device__ __forceinline__ uint32_t smem_u32(const void* p) {
    return (uint32_t)__cvta_generic_to_shared(p);
}
__device__ __forceinline__ void cp_async16(void* dst, const void* src) {
    asm volatile("cp.async.cg.shared.global [%0], [%1], 16;\n"
                 :: "r"(smem_u32(dst)), "l"(src));
}
__device__ __forceinline__ void cp_commit() {
    asm volatile("cp.async.commit_group;\n" ::: "memory");
}
__device__ __forceinline__ void cp_wait1() {
    asm volatile("cp.async.wait_group 1;\n" ::: "memory");
}
__device__ __forceinline__ void ldsm_x4(uint32_t& r0, uint32_t& r1,
                                        uint32_t& r2, uint32_t& r3, uint32_t addr) {
    asm volatile("ldmatrix.sync.aligned.m8n8.x4.shared.b16 {%0,%1,%2,%3}, [%4];\n"
                 : "=r"(r0), "=r"(r1), "=r"(r2), "=r"(r3) : "r"(addr));
}
__device__ __forceinline__ void mma16816(float* d, const uint32_t* a, const uint32_t* b) {
    asm volatile(
        "mma.sync.aligned.m16n8k16.row.col.f32.f16.f16.f32 "
        "{%0,%1,%2,%3}, {%4,%5,%6,%7}, {%8,%9}, {%0,%1,%2,%3};\n"
        : "+f"(d[0]), "+f"(d[1]), "+f"(d[2]), "+f"(d[3])
        : "r"(a[0]), "r"(a[1]), "r"(a[2]), "r"(a[3]), "r"(b[0]), "r"(b[1]));
}
// swizzled element offset within a [128][32]-half tile (16B chunks XOR'd)
__device__ __forceinline__ int swz(int r, int c) {
    return r * 32 + ((c ^ ((r >> 1) & 3)) << 3);
}

// ------------------------------------------------- fp16 tensor-core GEMM ----
// C[M,N] = A[M,K] * B[N,K]^T, A/B half K-contiguous, C fp32.
// EPI 0: store.  EPI 2: += aux[m*ldc+n] (residual).
template<int EPI>
__global__ void __launch_bounds__(256) hgemm(
    int M, int N, int K,
    const __half* __restrict__ A,
    const __half* __restrict__ B,
    float* __restrict__ C, int ldc,
    const float* __restrict__ aux)
{
    constexpr int BM = 128, BN = 128, BK = 32, ST = 3;
    __shared__ __half sA[ST][BM * BK];
    __shared__ __half sB[ST][BN * BK];

    const int tid  = threadIdx.x;
    const int wid  = tid >> 5, lane = tid & 31;
    const int wm   = wid >> 1, wn = wid & 1;        // 4 x 2 warp grid
    const int m0   = blockIdx.y * BM, n0 = blockIdx.x * BN;
    const int k_tiles = K / BK;

    // per-thread stage-load mapping: 2 chunks of A + 2 of B
    const int cid0 = tid, cid1 = tid + 256;
    const int ra0 = cid0 >> 2, ca0 = cid0 & 3;
    const int ra1 = cid1 >> 2, ca1 = cid1 & 3;

    float acc[2][8][4];
    #pragma unroll
    for (int i = 0; i < 2; i++)
        #pragma unroll
        for (int j = 0; j < 8; j++)
            #pragma unroll
            for (int v = 0; v < 4; v++) acc[i][j][v] = 0.f;

    auto load_stage = [&](int s, int kt) {
        const __half* gA = A + (size_t)m0 * K + kt * BK;
        const __half* gB = B + (size_t)n0 * K + kt * BK;
        cp_async16(&sA[s][swz(ra0, ca0)], gA + (size_t)ra0 * K + ca0 * 8);
        cp_async16(&sA[s][swz(ra1, ca1)], gA + (size_t)ra1 * K + ca1 * 8);
        cp_async16(&sB[s][swz(ra0, ca0)], gB + (size_t)ra0 * K + ca0 * 8);
        cp_async16(&sB[s][swz(ra1, ca1)], gB + (size_t)ra1 * K + ca1 * 8);
    };

    load_stage(0, 0); cp_commit();
    load_stage(1, 1); cp_commit();

    const int fr = lane & 15;        // fragment row within 16
    const int fc = lane >> 4;        // fragment k-chunk add

    for (int kt = 0; kt < k_tiles; kt++) {
        cp_wait1();
        __syncthreads();
        const int nk = kt + ST - 1;
        if (nk < k_tiles) load_stage(nk % ST, nk);
        cp_commit();

        const int s = kt % ST;
        #pragma unroll
        for (int ks = 0; ks < 2; ks++) {
            uint32_t af[2][4];
            uint32_t bf[8][2];
            const int c0 = ks * 2 + fc;
            #pragma unroll
            for (int mt = 0; mt < 2; mt++) {
                const int r = wm * 32 + mt * 16 + fr;
                ldsm_x4(af[mt][0], af[mt][1], af[mt][2], af[mt][3],
                        smem_u32(&sA[s][swz(r, c0)]));
            }
            #pragma unroll
            for (int nt2 = 0; nt2 < 4; nt2++) {
                const int r = wn * 64 + nt2 * 16 + fr;
                uint32_t r0, r1, r2, r3;
                ldsm_x4(r0, r1, r2, r3, smem_u32(&sB[s][swz(r, c0)]));
                bf[nt2 * 2][0] = r0; bf[nt2 * 2 + 1][0] = r1;
                bf[nt2 * 2][1] = r2; bf[nt2 * 2 + 1][1] = r3;
            }
            #pragma unroll
            for (int mt = 0; mt < 2; mt++)
                #pragma unroll
                for (int nt = 0; nt < 8; nt++)
                    mma16816(acc[mt][nt], af[mt], bf[nt]);
        }
        __syncthreads();
    }

    // epilogue (M, N multiples of 128: no guards)
    #pragma unroll
    for (int mt = 0; mt < 2; mt++) {
        const int row = m0 + wm * 32 + mt * 16 + (lane >> 2);
        #pragma unroll
        for (int nt = 0; nt < 8; nt++) {
            const int col = n0 + wn * 64 + nt * 8 + (lane & 3) * 2;
            float2 v0 = make_float2(acc[mt][nt][0], acc[mt][nt][1]);
            float2 v1 = make_float2(acc[mt][nt][2], acc[mt][nt][3]);
            if (EPI == 2) {
                const float2 a0 = *(const float2*)&aux[(size_t)row * ldc + col];
                const float2 a1 = *(const float2*)&aux[(size_t)(row + 8) * ldc + col];
                v0.x += a0.x; v0.y += a0.y; v1.x += a1.x; v1.y += a1.y;
            }
            *(float2*)&C[(size_t)row * ldc + col]       = v0;
            *(float2*)&C[(size_t)(row + 8) * ldc + col] = v1;
        }
    }
}

// --------------------------------------------------------------- f32->f16 ---
__global__ void f2h_kernel(const float4* __restrict__ in, uint2* __restrict__ out, int n4)
{
    const int i = blockIdx.x * blockDim.x + threadIdx.x;
    if (i < n4) {
        float4 v = in[i];
        __half2 a = __floats2half2_rn(v.x, v.y);
        __half2 b = __floats2half2_rn(v.z, v.w);
        uint2 o;
        o.x = *(uint32_t*)&a; o.y = *(uint32_t*)&b;
        out[i] = o;
    }
}

// ------------------------------------------------------------- layernorm ----
__global__ void ln_kernel(const float* __restrict__ x,
                          const float* __restrict__ g,
                          const float* __restrict__ be,
                          __half* __restrict__ o)
{
    __shared__ float sred[64];
    const int row = blockIdx.x;
    const float4* xr = reinterpret_cast<const float4*>(x + (size_t)row * D_MODEL);
    float4 v = xr[threadIdx.x];
    float s = v.x + v.y + v.z + v.w;
    float q = v.x*v.x + v.y*v.y + v.z*v.z + v.w*v.w;
    #pragma unroll
    for (int off = 16; off; off >>= 1) {
        s += __shfl_xor_sync(0xffffffffu, s, off);
        q += __shfl_xor_sync(0xffffffffu, q, off);
    }
    const int warp = threadIdx.x >> 5, lane = threadIdx.x & 31;
    if (lane == 0) { sred[warp] = s; sred[32 + warp] = q; }
    __syncthreads();
    if (threadIdx.x == 0) {
        float ts = 0.f, tq = 0.f;
        #pragma unroll
        for (int i = 0; i < 8; i++) { ts += sred[i]; tq += sred[32 + i]; }
        float mean = ts * (1.f / D_MODEL);
        float var  = tq * (1.f / D_MODEL) - mean * mean;
        sred[0] = mean;
        sred[1] = rsqrtf(var + 1e-5f);
    }
    __syncthreads();
    const float mean = sred[0], inv = sred[1];
    float4 gg = reinterpret_cast<const float4*>(g)[threadIdx.x];
    float4 bb = reinterpret_cast<const float4*>(be)[threadIdx.x];
    float o0 = (v.x - mean) * inv * gg.x + bb.x;
    float o1 = (v.y - mean) * inv * gg.y + bb.y;
    float o2 = (v.z - mean) * inv * gg.z + bb.z;
    float o3 = (v.w - mean) * inv * gg.w + bb.w;
    __half2 h01 = __floats2half2_rn(o0, o1);
    __half2 h23 = __floats2half2_rn(o2, o3);
    uint2 packed;
    packed.x = *(uint32_t*)&h01; packed.y = *(uint32_t*)&h23;
    reinterpret_cast<uint2*>(o + (size_t)row * D_MODEL)[threadIdx.x] = packed;
}

// ------------------------------------------------------------- SIMT sgemm ---
// (kept for dt_proj; K=64 so tensor pipeline not worth it yet)
template<int BM, int BN, int BK, int TM, int TN, int NTH>
__global__ void __launch_bounds__(NTH) sgemm_nt(
    int M, int N, int K,
    const float* __restrict__ A, int lda,
    const float* __restrict__ Bm, int ldb,
    float* __restrict__ C, int ldc,
    int epi, const float* __restrict__ aux)
{
    __shared__ float As[BK][BM];
    __shared__ float Bs[BK][BN];
    const int tid = threadIdx.x;
    const int m0 = blockIdx.y * BM;
    const int n0 = blockIdx.x * BN;
    constexpr int TX = BN / TN;
    const int tx = tid % TX, ty = tid / TX;

    float acc[TM][TN];
    #pragma unroll
    for (int i = 0; i < TM; i++)
        #pragma unroll
        for (int j = 0; j < TN; j++) acc[i][j] = 0.f;

    constexpr int AVEC = (BM * BK / NTH >= 4) ? 4 : 2;
    constexpr int A_TPR = BK / AVEC;
    constexpr int A_RPP = NTH / A_TPR;
    constexpr int BVEC = (BN * BK / NTH >= 4) ? 4 : 2;
    constexpr int B_TPR = BK / BVEC;
    constexpr int B_RPP = NTH / B_TPR;

    for (int k0 = 0; k0 < K; k0 += BK) {
        __syncthreads();
        #pragma unroll
        for (int r0 = 0; r0 < BM; r0 += A_RPP) {
            int row = r0 + tid / A_TPR;
            int kc  = (tid % A_TPR) * AVEC;
            const float* src = A + (size_t)(m0 + row) * lda + k0 + kc;
            if (AVEC == 4) {
                float4 v = *reinterpret_cast<const float4*>(src);
                As[kc    ][row] = v.x; As[kc + 1][row] = v.y;
                As[kc + 2][row] = v.z; As[kc + 3][row] = v.w;
            } else {
                float2 v = *reinterpret_cast<const float2*>(src);
                As[kc][row] = v.x; As[kc + 1][row] = v.y;
            }
        }
        #pragma unroll
        for (int r0 = 0; r0 < BN; r0 += B_RPP) {
            int row = r0 + tid / B_TPR;
            int kc  = (tid % B_TPR) * BVEC;
            int n   = n0 + row;
            if (BVEC == 4) {
                float4 v = (n < N)
                    ? *reinterpret_cast<const float4*>(Bm + (size_t)n * ldb + k0 + kc)
                    : make_float4(0.f, 0.f, 0.f, 0.f);
                Bs[kc    ][row] = v.x; Bs[kc + 1][row] = v.y;
                Bs[kc + 2][row] = v.z; Bs[kc + 3][row] = v.w;
            } else {
                float2 v = (n < N)
                    ? *reinterpret_cast<const float2*>(Bm + (size_t)n * ldb + k0 + kc)
                    : make_float2(0.f, 0.f);
                Bs[kc][row] = v.x; Bs[kc + 1][row] = v.y;
            }
        }
        __syncthreads();
        #pragma unroll
        for (int k = 0; k < BK; k++) {
            float a[TM], b[TN];
            #pragma unroll
            for (int v = 0; v < TM / 4; v++) {
                float4 t = *reinterpret_cast<const float4*>(&As[k][ty * 4 + v * (BM / 2)]);
                a[v*4+0] = t.x; a[v*4+1] = t.y; a[v*4+2] = t.z; a[v*4+3] = t.w;
            }
            #pragma unroll
            for (int v = 0; v < TN / 4; v++) {
                float4 t = *reinterpret_cast<const float4*>(&Bs[k][tx * 4 + v * (BN / 2)]);
                b[v*4+0] = t.x; b[v*4+1] = t.y; b[v*4+2] = t.z; b[v*4+3] = t.w;
            }
            #pragma unroll
            for (int i = 0; i < TM; i++)
                #pragma unroll
                for (int j = 0; j < TN; j++)
                    acc[i][j] = fmaf(a[i], b[j], acc[i][j]);
        }
    }
    #pragma unroll
    for (int i = 0; i < TM; i++) {
        int m = m0 + ty * 4 + (i & 3) + (i >> 2) * (BM / 2);
        #pragma unroll
        for (int j = 0; j < TN; j++) {
            int n = n0 + tx * 4 + (j & 3) + (j >> 2) * (BN / 2);
            if (n < N) {
                float v = acc[i][j];
                if (epi == 1) {
                    v += aux[n];
                    v = (v > 20.f) ? v : log1pf(expf(v));
                } else if (epi == 2) {
                    v += aux[(size_t)m * ldc + n];
                }
                C[(size_t)m * ldc + n] = v;
            }
        }
    }
}

// -------------------------------------------------- depthwise conv + SiLU ---
__global__ void conv_silu_kernel(const float* __restrict__ xz,
                                 const float* __restrict__ w,
                                 const float* __restrict__ bias,
                                 float* __restrict__ out)
{
    const int idx = blockIdx.x * blockDim.x + threadIdx.x;
    if (idx >= B_SZ * SEQ_L * D_INNER) return;
    const int c = idx & (D_INNER - 1);
    const int t = (idx >> 11) & (SEQ_L - 1);
    const int b = idx >> 22;
    const float* col = xz + (size_t)(b * SEQ_L) * (2 * D_INNER) + c;
    const float4 wv = reinterpret_cast<const float4*>(w)[c];
    float acc = bias[c];
    if (t >= 3) {
        acc += col[(size_t)(t - 3) * 4096] * wv.x
             + col[(size_t)(t - 2) * 4096] * wv.y
             + col[(size_t)(t - 1) * 4096] * wv.z
             + col[(size_t)(t    ) * 4096] * wv.w;
    } else {
        const float wj[4] = {wv.x, wv.y, wv.z, wv.w};
        #pragma unroll
        for (int j = 0; j < 4; j++) {
            int tt = t - 3 + j;
            if (tt >= 0) acc += col[(size_t)tt * 4096] * wj[j];
        }
    }
    const float sig = 1.f / (1.f + expf(-acc));
    out[idx] = acc * sig;
}

// ---------------------------------------------- x_proj split-K + reduce -----
__global__ void __launch_bounds__(256) xproj_part(
    const float* __restrict__ A,      // xconv [4096, 2048]
    const float* __restrict__ B,      // x_proj_w [96, 2048]
    float* __restrict__ P)            // [8][4096*96]
{
    constexpr int BM = 64, BK = 8, KSL = 2048 / 8;
    __shared__ float As[BK][BM];
    __shared__ float Bs[BK][96 + 4];
    const int tid = threadIdx.x;
    const int m0 = blockIdx.y * BM;
    const int kb = blockIdx.x * KSL;
    const int ty = tid >> 4, tx = tid & 15;  // ty 0..15 (4 rows), tx 0..15 (6 cols)

    float acc[4][6];
    #pragma unroll
    for (int i = 0; i < 4; i++)
        #pragma unroll
        for (int j = 0; j < 6; j++) acc[i][j] = 0.f;

    for (int k0 = 0; k0 < KSL; k0 += BK) {
        __syncthreads();
        {
            int r = tid >> 2, kc = (tid & 3) * 2;
            float2 v = *(const float2*)(A + (size_t)(m0 + r) * 2048 + kb + k0 + kc);
            As[kc][r] = v.x; As[kc + 1][r] = v.y;
        }
        #pragma unroll
        for (int i = tid; i < 96 * 8; i += 256) {
            int r = i >> 3, kk = i & 7;
            Bs[kk][r] = B[(size_t)r * 2048 + kb + k0 + kk];
        }
        __syncthreads();
        #pragma unroll
        for (int k = 0; k < BK; k++) {
            float a[4], b[6];
            #pragma unroll
            for (int i = 0; i < 4; i++) a[i] = As[k][ty * 4 + i];
            #pragma unroll
            for (int j = 0; j < 6; j++) b[j] = Bs[k][tx * 6 + j];
            #pragma unroll
            for (int i = 0; i < 4; i++)
                #pragma unroll
                for (int j = 0; j < 6; j++)
                    acc[i][j] = fmaf(a[i], b[j], acc[i][j]);
        }
    }
    float* out = P + (size_t)blockIdx.x * NTOK * 96;
    #pragma unroll
    for (int i = 0; i < 4; i++)
        #pragma unroll
        for (int j = 0; j < 6; j++)
            out[(size_t)(m0 + ty * 4 + i) * 96 + tx * 6 + j] = acc[i][j];
}

__global__ void xproj_reduce(const float* __restrict__ P, float* __restrict__ xdbl)
{
    const int i = blockIdx.x * blockDim.x + threadIdx.x;
    if (i >= NTOK * 96) return;
    float s = 0.f;
    #pragma unroll
    for (int k = 0; k < 8; k++) s += P[(size_t)k * NTOK * 96 + i];
    xdbl[i] = s;
}

// ---------------------------------------------- selective scan (fused) ------
__global__ void __launch_bounds__(256) scan_fuse_kernel(
    const float* __restrict__ dt,
    const float* __restrict__ xconv,
    const float* __restrict__ xdbl,
    const float* __restrict__ xz,
    const float* __restrict__ A_log,
    const float* __restrict__ Dp,
    __half* __restrict__ y)
{
    const int b     = blockIdx.x >> 7;
    const int dbase = (blockIdx.x & 127) << 4;
    const int lane  = threadIdx.x & 31;
    const int warp  = threadIdx.x >> 5;
    const int s     = lane & 15;
    const int half  = lane >> 4;
    const int d     = dbase + warp * 2 + half;

    const float Acoef = -expf(A_log[d * D_STATE + s]);
    const float Dv    = Dp[d];
    float h = 0.f;

    const float* dt_p = dt    + (size_t)b * SEQ_L * D_INNER + d;
    const float* x_p  = xconv + (size_t)b * SEQ_L * D_INNER + d;
    const float* B_p  = xdbl  + (size_t)b * SEQ_L * 96 + DT_RANK + s;
    const float* C_p  = B_p + D_STATE;
    const float* z_p  = xz    + (size_t)b * SEQ_L * (2 * D_INNER) + D_INNER + d;
    __half*      y_p  = y     + (size_t)b * SEQ_L * D_INNER + d;

    #pragma unroll 4
    for (int t = 0; t < SEQ_L; ++t) {
        const float dtv = dt_p[(size_t)t * D_INNER];
        const float xv  = x_p [(size_t)t * D_INNER];
        const float Bv  = B_p [(size_t)t * 96];
        const float Cv  = C_p [(size_t)t * 96];

        const float p = __expf(Acoef * dtv);
        h = fmaf(p, h, dtv * Bv * xv);
        float yp = h * Cv;
        yp += __shfl_xor_sync(0xffffffffu, yp, 8);
        yp += __shfl_xor_sync(0xffffffffu, yp, 4);
        yp += __shfl_xor_sync(0xffffffffu, yp, 2);
        yp += __shfl_xor_sync(0xffffffffu, yp, 1);
        if (s == 0) {
            const float zv  = z_p[(size_t)t * (2 * D_INNER)];
            const float sig = 1.f / (1.f + __expf(-zv));
            y_p[(size_t)t * D_INNER] = __float2half((yp + xv * Dv) * (zv * sig));
        }
    }
}

// ----------------------------------------------------------------- launch ---
extern "C" void kernel_launch(void* const* d_in, const int* in_sizes, int n_in,
                              void* d_out, int out_size)
{
    const float* hs    = (const float*)d_in[0];
    const float* ln_g  = (const float*)d_in[1];
    const float* ln_b  = (const float*)d_in[2];
    const float* inw   = (const float*)d_in[3];   // [4096,1024]
    const float* convw = (const float*)d_in[4];
    const float* convb = (const float*)d_in[5];
    const float* xpw   = (const float*)d_in[6];   // [96,2048]
    const float* dtw   = (const float*)d_in[7];   // [2048,64]
    const float* dtb   = (const float*)d_in[8];
    const float* alog  = (const float*)d_in[9];
    const float* Dv    = (const float*)d_in[10];
    const float* outw  = (const float*)d_in[11];  // [1024,2048]

    __half *hnorm_h, *y_h, *inw_h, *outw_h;
    float *xz, *xconv, *xdbl, *xpart, *dtbuf;
    cudaGetSymbolAddress((void**)&hnorm_h, g_hnorm_h);
    cudaGetSymbolAddress((void**)&xz,      g_xz);
    cudaGetSymbolAddress((void**)&xconv,   g_xconv);
    cudaGetSymbolAddress((void**)&xdbl,    g_xdbl);
    cudaGetSymbolAddress((void**)&xpart,   g_xpart);
    cudaGetSymbolAddress((void**)&dtbuf,   g_dt);
    cudaGetSymbolAddress((void**)&y_h,     g_y_h);
    cudaGetSymbolAddress((void**)&inw_h,   g_w_in_h);
    cudaGetSymbolAddress((void**)&outw_h,  g_w_out_h);

    // 0. weight conversions fp32 -> fp16
    f2h_kernel<<<(2 * D_INNER * D_MODEL / 4 + 255) / 256, 256>>>(
        (const float4*)inw, (uint2*)inw_h, 2 * D_INNER * D_MODEL / 4);
    f2h_kernel<<<(D_MODEL * D_INNER / 4 + 255) / 256, 256>>>(
        (const float4*)outw, (uint2*)outw_h, D_MODEL * D_INNER / 4);

    // 1. LayerNorm (emits fp16)
    ln_kernel<<<NTOK, 256>>>(hs, ln_g, ln_b, hnorm_h);

    // 2. in_proj (tensor cores): xz[4096,4096] fp32 = hnorm_h @ inw_h^T
    hgemm<0><<<dim3(32, 32), 256>>>(NTOK, 4096, 1024, hnorm_h, inw_h, xz, 4096, nullptr);

    // 3. depthwise causal conv + SiLU
    conv_silu_kernel<<<(B_SZ * SEQ_L * D_INNER) / 256, 256>>>(xz, convw, convb, xconv);

    // 4. x_proj split-K (8 slices) + reduce
    xproj_part<<<dim3(8, 64), 256>>>(xconv, xpw, xpart);
    xproj_reduce<<<(NTOK * 96 + 255) / 256, 256>>>(xpart, xdbl);

    // 5. dt_proj + softplus (SIMT, K=64)
    sgemm_nt<128,128,8,8,8,256><<<dim3(16, 32), 256>>>(
        NTOK, 2048, 64, xdbl, 96, dtw, 64, dtbuf, 2048, 1, dtb);

    // 6. selective scan fused with (+x*D)*silu(z), emits fp16 y
    scan_fuse_kernel<<<256, 256>>>(dtbuf, xconv, xdbl, xz, alog, Dv, y_h);

    // 7. out_proj + residual (tensor cores) -> d_out fp32
    hgemm<2><<<dim3(8, 32), 256>>>(NTOK, 1024, 2048, y_h, outw_h, (float*)d_out, 1024, hs);
}